// round 16
// baseline (speedup 1.0000x reference)
#include <cuda_runtime.h>
#include <cuda_fp16.h>
#include <cstdint>

#define NNODES 50000
#define NEDGES 400000
#define MP     50048
#define NOUT   256
#define SCAN_BLOCKS 49    // 49*1024 >= NNODES+1

// ---------------- static device scratch (no allocations allowed) ----------------
__device__ int    g_deg[NNODES];
__device__ int    g_cnt[NNODES];
__device__ int    g_fill[NNODES];
__device__ float  g_dinv[NNODES];
__device__ int    g_rowptr[NNODES + 1];   // block-LOCAL exclusive scan
__device__ int    g_bsum[SCAN_BLOCKS];
__device__ int    g_boff[SCAN_BLOCKS];    // global offset of each scan block
__device__ int    g_done;                 // scan1 completion counter
__device__ int    g_col[NEDGES];
__device__ float  g_wval[NEDGES];
// fp16 activation / weight storage
__device__ __half g_xh  [(size_t)MP * 128];
__device__ __half g_h1h [(size_t)MP * 256];
__device__ __half g_h2h [(size_t)MP * 256];
__device__ __half g_aggh[(size_t)MP * 256];
__device__ __half g_wth [256 * 128 * 2 + 256 * 256 * 4];   // Wt[n][k] fp16

#define WT_OFF_10 0
#define WT_OFF_11 (256 * 128)
#define WT_OFF_20 (256 * 128 * 2)
#define WT_OFF_21 (WT_OFF_20 + 256 * 256)
#define WT_OFF_30 (WT_OFF_21 + 256 * 256)
#define WT_OFF_31 (WT_OFF_30 + 256 * 256)

#define SEL_X   0
#define SEL_H1  1
#define SEL_H2  2

__device__ __forceinline__ const __half* sel_ch(int SEL) {
    switch (SEL) {
        case SEL_H1: return g_h1h;
        case SEL_H2: return g_h2h;
        default:     return g_xh;
    }
}

// ---------------- mma / ldmatrix / cp.async helpers ----------------
__device__ __forceinline__ void mma_f16(float* c, const uint32_t* a, const uint32_t* b) {
    asm volatile(
        "mma.sync.aligned.m16n8k16.row.col.f32.f16.f16.f32 "
        "{%0,%1,%2,%3}, {%4,%5,%6,%7}, {%8,%9}, {%0,%1,%2,%3};"
        : "+f"(c[0]), "+f"(c[1]), "+f"(c[2]), "+f"(c[3])
        : "r"(a[0]), "r"(a[1]), "r"(a[2]), "r"(a[3]), "r"(b[0]), "r"(b[1]));
}
__device__ __forceinline__ void ldsm_x4(uint32_t& r0, uint32_t& r1, uint32_t& r2,
                                        uint32_t& r3, uint32_t addr) {
    asm volatile("ldmatrix.sync.aligned.m8n8.x4.shared.b16 {%0,%1,%2,%3}, [%4];"
                 : "=r"(r0), "=r"(r1), "=r"(r2), "=r"(r3) : "r"(addr));
}
__device__ __forceinline__ uint32_t smem_u32(const void* p) {
    uint32_t a;
    asm("{ .reg .u64 t; cvta.to.shared.u64 t, %1; cvt.u32.u64 %0, t; }" : "=r"(a) : "l"(p));
    return a;
}
__device__ __forceinline__ void cp_async16(uint32_t dst, const void* src, bool valid) {
    int sz = valid ? 16 : 0;   // src-size 0 -> zero-fill
    asm volatile("cp.async.cg.shared.global [%0], [%1], 16, %2;"
                 :: "r"(dst), "l"(src), "r"(sz) : "memory");
}
#define CP_COMMIT()  asm volatile("cp.async.commit_group;" ::: "memory")
#define CP_WAIT2()   asm volatile("cp.async.wait_group 2;" ::: "memory")
#define CP_WAIT1()   asm volatile("cp.async.wait_group 1;" ::: "memory")
#define CP_WAIT0()   asm volatile("cp.async.wait_group 0;" ::: "memory")

// ---------------- fused prep: init counters + x->fp16 + weight transpose ---------
#define NB_X2H 12512                      // MP*64 half2 / 256
#define NB_INIT 196                       // ceil(NNODES/256)
#define NB_TR   384                       // 6 matrices * 8 kb * 8 nb
__global__ void k_prep(const float* __restrict__ x,
                       const float* __restrict__ w10, const float* __restrict__ w11,
                       const float* __restrict__ w20, const float* __restrict__ w21,
                       const float* __restrict__ w30, const float* __restrict__ w31)
{
    const int b = blockIdx.x;
    if (b < NB_X2H) {
        // x -> fp16 with zero padding
        const size_t i = (size_t)b * 256 + threadIdx.x;   // half2 index
        int row = (int)(i >> 6);
        __half2 v = __float2half2_rn(0.f);
        if (row < NNODES) {
            float2 f = reinterpret_cast<const float2*>(x)[i];
            v = __floats2half2_rn(f.x, f.y);
        }
        reinterpret_cast<__half2*>(g_xh)[i] = v;
    } else if (b < NB_X2H + NB_INIT) {
        const int i = (b - NB_X2H) * 256 + threadIdx.x;
        if (i < NNODES) { g_deg[i] = 0; g_cnt[i] = 0; g_fill[i] = 0; }
        if (i == 0) g_done = 0;
    } else {
        // weight transpose + fp16: g_wth[n][k] = W[k][n]
        __shared__ float sh[32][33];
        const int idx = b - (NB_X2H + NB_INIT);
        const int m   = idx / 64;
        const int rem = idx % 64;
        const int kb  = (rem / 8) * 32;
        const int nb  = (rem % 8) * 32;
        const float* W; int K, off;
        switch (m) {
            case 0: W = w10; K = 128; off = WT_OFF_10; break;
            case 1: W = w11; K = 128; off = WT_OFF_11; break;
            case 2: W = w20; K = 256; off = WT_OFF_20; break;
            case 3: W = w21; K = 256; off = WT_OFF_21; break;
            case 4: W = w30; K = 256; off = WT_OFF_30; break;
            default: W = w31; K = 256; off = WT_OFF_31; break;
        }
        if (kb >= K) return;
        const int tx = threadIdx.x & 31, ty0 = threadIdx.x >> 5;   // 32 x 8
        for (int ty = ty0; ty < 32; ty += 8)
            sh[ty][tx] = W[(size_t)(kb + ty) * NOUT + nb + tx];
        __syncthreads();
        for (int ty = ty0; ty < 32; ty += 8)
            g_wth[(size_t)off + (size_t)(nb + ty) * K + kb + tx] = __float2half(sh[tx][ty]);
    }
}

// edge_index is int32 (JAX default config disables x64)
__global__ void k_deg(const int* __restrict__ ei) {
    int e = blockIdx.x * blockDim.x + threadIdx.x;
    if (e < NEDGES) {
        int s = ei[e];
        int d = ei[NEDGES + e];
        if (s != d && (unsigned)s < NNODES && (unsigned)d < NNODES) {
            atomicAdd(&g_deg[s], 1);
            atomicAdd(&g_cnt[d], 1);
        }
    }
}

// scan phase 1: block-local exclusive scan via warp shuffles; dinv; and the
// LAST block to finish also scans the 49 block sums into g_boff (no extra launch).
__global__ void k_scan1() {
    __shared__ int wsum[32];
    __shared__ int lastFlag;
    const int t    = threadIdx.x;
    const int lane = t & 31;
    const int wid  = t >> 5;
    const int i    = blockIdx.x * 1024 + t;

    if (i < NNODES) {
        int dg = g_deg[i];
        g_dinv[i] = (dg > 0) ? rsqrtf((float)dg) : 0.0f;
    }

    int v = (i < NNODES) ? g_cnt[i] : 0;
    // inclusive warp scan
    int x = v;
#pragma unroll
    for (int off = 1; off < 32; off <<= 1) {
        int y = __shfl_up_sync(0xFFFFFFFFu, x, off);
        if (lane >= off) x += y;
    }
    if (lane == 31) wsum[wid] = x;
    __syncthreads();
    if (wid == 0) {
        int s = wsum[lane];
#pragma unroll
        for (int off = 1; off < 32; off <<= 1) {
            int y = __shfl_up_sync(0xFFFFFFFFu, s, off);
            if (lane >= off) s += y;
        }
        wsum[lane] = s;   // inclusive over warp sums
    }
    __syncthreads();
    int prefix = ((wid > 0) ? wsum[wid - 1] : 0) + (x - v);   // block-local exclusive
    if (i <= NNODES) g_rowptr[i] = prefix;
    if (t == 1023) g_bsum[blockIdx.x] = wsum[31];

    // last-block-done: scan the block sums into g_boff
    __syncthreads();   // ensure g_bsum store issued by t=1023 is ordered below
    if (t == 0) {
        __threadfence();
        int prev = atomicAdd(&g_done, 1);
        lastFlag = (prev == SCAN_BLOCKS - 1) ? 1 : 0;
    }
    __syncthreads();
    if (lastFlag && t == 0) {
        int s = 0;
        for (int b = 0; b < SCAN_BLOCKS; ++b) { g_boff[b] = s; s += g_bsum[b]; }
        __threadfence();
    }
}

__global__ void k_fill(const int* __restrict__ ei) {
    int e = blockIdx.x * blockDim.x + threadIdx.x;
    if (e < NEDGES) {
        int s = ei[e];
        int d = ei[NEDGES + e];
        if (s != d && (unsigned)s < NNODES && (unsigned)d < NNODES) {
            int pos = atomicAdd(&g_fill[d], 1);
            int idx = g_rowptr[d] + g_boff[d >> 10] + pos;
            g_col[idx]  = s;
            g_wval[idx] = -g_dinv[s] * g_dinv[d];
        }
    }
}

// ---------------- SpMM (fp16 in/out, fp32 accum) ----------------
// 32 rows per block: slices of W8 = F/8 lanes each process 4 consecutive rows
// serially (averages the Poisson degree tail), one uint4 per lane per edge.
#define SPMM_RPB 32          // rows per block
#define SPMM_RPS 4           // rows per slice (serial)
template <int F, int SEL_IN>
__global__ void k_spmm(int dummy) {
    const uint4* __restrict__ in = reinterpret_cast<const uint4*>(sel_ch(SEL_IN));
    const int W8    = F / 8;
    const int slice = threadIdx.x / W8;
    const int t     = threadIdx.x % W8;
    const int row0  = blockIdx.x * SPMM_RPB + slice * SPMM_RPS;

#pragma unroll
    for (int r = 0; r < SPMM_RPS; ++r) {
        const int row = row0 + r;
        if (row >= NNODES) return;
        const int beg = g_rowptr[row]     + g_boff[row >> 10];
        const int end = g_rowptr[row + 1] + g_boff[(row + 1) >> 10];

        float ac[8];
#pragma unroll
        for (int q = 0; q < 8; ++q) ac[q] = 0.f;

        int j = beg;
        for (; j + 3 < end; j += 4) {
            float w0 = g_wval[j];     int c0 = g_col[j];
            float w1 = g_wval[j + 1]; int c1 = g_col[j + 1];
            float w2 = g_wval[j + 2]; int c2 = g_col[j + 2];
            float w3 = g_wval[j + 3]; int c3 = g_col[j + 3];
            uint4 v0 = __ldg(&in[(size_t)c0 * W8 + t]);
            uint4 v1 = __ldg(&in[(size_t)c1 * W8 + t]);
            uint4 v2 = __ldg(&in[(size_t)c2 * W8 + t]);
            uint4 v3 = __ldg(&in[(size_t)c3 * W8 + t]);
            const __half2* h0 = reinterpret_cast<const __half2*>(&v0);
            const __half2* h1 = reinterpret_cast<const __half2*>(&v1);
            const __half2* h2 = reinterpret_cast<const __half2*>(&v2);
            const __half2* h3 = reinterpret_cast<const __half2*>(&v3);
#pragma unroll
            for (int q = 0; q < 4; ++q) {
                float2 f0 = __half22float2(h0[q]);
                float2 f1 = __half22float2(h1[q]);
                float2 f2 = __half22float2(h2[q]);
                float2 f3 = __half22float2(h3[q]);
                ac[2*q]   += (w0 * f0.x + w1 * f1.x) + (w2 * f2.x + w3 * f3.x);
                ac[2*q+1] += (w0 * f0.y + w1 * f1.y) + (w2 * f2.y + w3 * f3.y);
            }
        }
        for (; j < end; ++j) {
            float w = g_wval[j]; int c = g_col[j];
            uint4 v = __ldg(&in[(size_t)c * W8 + t]);
            const __half2* h = reinterpret_cast<const __half2*>(&v);
#pragma unroll
            for (int q = 0; q < 4; ++q) {
                float2 f = __half22float2(h[q]);
                ac[2*q]   += w * f.x;
                ac[2*q+1] += w * f.y;
            }
        }

        uint4 o;
        __half2* oh = reinterpret_cast<__half2*>(&o);
#pragma unroll
        for (int q = 0; q < 4; ++q) oh[q] = __floats2half2_rn(ac[2*q], ac[2*q+1]);
        reinterpret_cast<uint4*>(g_aggh)[(size_t)row * W8 + t] = o;
    }
}

// ---------------- fp16 HMMA fused dual-GEMM: cp.async 4-stage, swizzled ----------
#define BM 128
#define BN 128
#define BK 32
#define STG_WORDS (128 * 16)        // words per stage per operand
#define STG_BYTES (STG_WORDS * 4)   // 8192
#define NSTG 4
#define SMEM_DYN (NSTG * 2 * STG_BYTES)   // 65536

template <int SEL_A0, int SEL_C>
__global__ void __launch_bounds__(256, 2) k_gemm(
    int wtOff0, int wtOff1,
    const float* __restrict__ bias, float* __restrict__ C_ext,
    int K, int do_relu)
{
    extern __shared__ uint32_t smem_dyn[];
    const __half* __restrict__ A0 = sel_ch(SEL_A0);
    const __half* __restrict__ A1 = g_aggh;
    const __half* __restrict__ W0 = g_wth + wtOff0;
    const __half* __restrict__ W1 = g_wth + wtOff1;

    const int tid  = threadIdx.x;        // 0..255
    const int warp = tid >> 5;           // 0..7
    const int lane = tid & 31;
    const int gid  = lane >> 2;          // 0..7
    const int tig  = lane & 3;           // 0..3
    const int wm   = (warp & 3)  * 32;   // warp row offset (4 m-warps)
    const int wn   = (warp >> 2) * 64;   // warp col offset (2 n-warps)

    const int rowBase = blockIdx.x * BM;
    const int colBase = blockIdx.y * BN;

    // stager: row = tid>>1 (0..127); groups (tid&1)*2 + {0,1} (each 8 halves = 16B)
    const int sRow = tid >> 1;
    const int g0   = (tid & 1) * 2;
    const int swz  = (sRow >> 1) & 3;
    const bool aValid = (rowBase + sRow < NNODES);
    const __half* __restrict__ Arow0 = A0 + (size_t)(rowBase + sRow) * K;
    const __half* __restrict__ Arow1 = A1 + (size_t)(rowBase + sRow) * K;
    const __half* __restrict__ Brow0 = W0 + (size_t)(colBase + sRow) * K;
    const __half* __restrict__ Brow1 = W1 + (size_t)(colBase + sRow) * K;

    // ldmatrix lane addressing
    const int aLRow = wm + (lane & 7) + ((lane >> 3) & 1) * 8;   // + mt*16
    const int aG    = lane >> 4;                                  // k-group within k16
    const int bLRow = wn + (lane & 7) + (lane >> 4) * 8;          // + ntp*16
    const int bG    = (lane >> 3) & 1;

    const uint32_t asBase = smem_u32(&smem_dyn[0]);
    const uint32_t bsBase = asBase + NSTG * STG_BYTES;

    const int Kt = K / BK;     // tiles per pass
    const int T  = 2 * Kt;     // A0 pass then agg pass (T = 8 or 16)

    float acc[2][8][4];
#pragma unroll
    for (int mt = 0; mt < 2; ++mt)
#pragma unroll
        for (int nt = 0; nt < 8; ++nt)
#pragma unroll
            for (int q = 0; q < 4; ++q) acc[mt][nt][q] = 0.0f;

    // issue stage tn into ring buffer `buf`
    auto issue = [&](int tn, int buf) {
        const bool p2 = (tn >= Kt);
        const __half* __restrict__ Ar = p2 ? Arow1 : Arow0;
        const __half* __restrict__ Br = p2 ? Brow1 : Brow0;
        const int k0 = (tn - (p2 ? Kt : 0)) * BK;
        const uint32_t aB = asBase + (uint32_t)buf * STG_BYTES;
        const uint32_t bB = bsBase + (uint32_t)buf * STG_BYTES;
#pragma unroll
        for (int q = 0; q < 2; ++q) {
            const int g  = g0 + q;
            const int gp = g ^ swz;
            const uint32_t dOff = (uint32_t)((sRow * 16 + gp * 4) * 4);
            cp_async16(aB + dOff, Ar + k0 + g * 8, aValid);
            cp_async16(bB + dOff, Br + k0 + g * 8, true);
        }
        CP_COMMIT();
    };

    issue(0, 0);
    if (T > 1) issue(1, 1);
    if (T > 2) issue(2, 2);

#pragma unroll 1
    for (int t = 0; t < T; ++t) {
        if (t + 3 <= T - 1)      { CP_WAIT2(); }
        else if (t + 2 <= T - 1) { CP_WAIT1(); }
        else                     { CP_WAIT0(); }
        __syncthreads();
        // top barrier also seals all reads of buffer (t-1)%4 (done in iter t-1),
        // so the issue below may overwrite it; no bottom barrier needed.

        if (t + 3 < T) issue(t + 3, (t + 3) & (NSTG - 1));

        const uint32_t asC = asBase + (uint32_t)(t & (NSTG - 1)) * STG_BYTES;
        const uint32_t bsC = bsBase + (uint32_t)(t & (NSTG - 1)) * STG_BYTES;

#pragma unroll
        for (int kh = 0; kh < 2; ++kh) {
            uint32_t a[2][4], b[8][2];
#pragma unroll
            for (int mt = 0; mt < 2; ++mt) {
                const int row = aLRow + mt * 16;
                const int gp  = (kh * 2 + aG) ^ ((row >> 1) & 3);
                ldsm_x4(a[mt][0], a[mt][1], a[mt][2], a[mt][3],
                        asC + (uint32_t)((row * 16 + gp * 4) * 4));
            }
#pragma unroll
            for (int ntp = 0; ntp < 4; ++ntp) {
                const int row = bLRow + ntp * 16;
                const int gp  = (kh * 2 + bG) ^ ((row >> 1) & 3);
                ldsm_x4(b[2*ntp][0], b[2*ntp][1], b[2*ntp+1][0], b[2*ntp+1][1],
                        bsC + (uint32_t)((row * 16 + gp * 4) * 4));
            }
#pragma unroll
            for (int mt = 0; mt < 2; ++mt)
#pragma unroll
                for (int nt = 0; nt < 8; ++nt)
                    mma_f16(acc[mt][nt], a[mt], b[nt]);
        }
    }

    // ---- epilogue: bias + optional relu ----
    float2 bb[8];
#pragma unroll
    for (int nt = 0; nt < 8; ++nt)
        bb[nt] = *reinterpret_cast<const float2*>(&bias[colBase + wn + nt * 8 + 2 * tig]);

    if (SEL_C == SEL_X) {
        float* __restrict__ C = C_ext;
#pragma unroll
        for (int mt = 0; mt < 2; ++mt) {
            const int r0 = rowBase + wm + mt * 16 + gid;
            const int r1 = r0 + 8;
#pragma unroll
            for (int nt = 0; nt < 8; ++nt) {
                const int c = colBase + wn + nt * 8 + 2 * tig;
                float v0 = acc[mt][nt][0] + bb[nt].x;
                float v1 = acc[mt][nt][1] + bb[nt].y;
                float v2 = acc[mt][nt][2] + bb[nt].x;
                float v3 = acc[mt][nt][3] + bb[nt].y;
                if (do_relu) {
                    v0 = fmaxf(v0, 0.f); v1 = fmaxf(v1, 0.f);
                    v2 = fmaxf(v2, 0.f); v3 = fmaxf(v3, 0.f);
                }
                if (r0 < NNODES)
                    *reinterpret_cast<float2*>(&C[(size_t)r0 * NOUT + c]) = make_float2(v0, v1);
                if (r1 < NNODES)
                    *reinterpret_cast<float2*>(&C[(size_t)r1 * NOUT + c]) = make_float2(v2, v3);
            }
        }
    } else {
        __half* __restrict__ Ch = (SEL_C == SEL_H1) ? g_h1h : g_h2h;
#pragma unroll
        for (int mt = 0; mt < 2; ++mt) {
            const int r0 = rowBase + wm + mt * 16 + gid;
            const int r1 = r0 + 8;
#pragma unroll
            for (int nt = 0; nt < 8; ++nt) {
                const int c = colBase + wn + nt * 8 + 2 * tig;
                float v0 = acc[mt][nt][0] + bb[nt].x;
                float v1 = acc[mt][nt][1] + bb[nt].y;
                float v2 = acc[mt][nt][2] + bb[nt].x;
                float v3 = acc[mt][nt][3] + bb[nt].y;
                if (do_relu) {
                    v0 = fmaxf(v0, 0.f); v1 = fmaxf(v1, 0.f);
                    v2 = fmaxf(v2, 0.f); v3 = fmaxf(v3, 0.f);
                }
                *reinterpret_cast<__half2*>(&Ch[(size_t)r0 * NOUT + c]) = __floats2half2_rn(v0, v1);
                *reinterpret_cast<__half2*>(&Ch[(size_t)r1 * NOUT + c]) = __floats2half2_rn(v2, v3);
            }
        }
    }
}

// ---------------- launcher ----------------
extern "C" void kernel_launch(void* const* d_in, const int* in_sizes, int n_in,
                              void* d_out, int out_size)
{
    const float* x    = (const float*)d_in[0];
    const int*   ei   = (const int*)d_in[1];     // int32 (JAX x64 disabled)
    const float* W1_0 = (const float*)d_in[2];
    const float* W1_1 = (const float*)d_in[3];
    const float* b1   = (const float*)d_in[4];
    const float* W2_0 = (const float*)d_in[5];
    const float* W2_1 = (const float*)d_in[6];
    const float* b2   = (const float*)d_in[7];
    const float* W3_0 = (const float*)d_in[8];
    const float* W3_1 = (const float*)d_in[9];
    const float* b3   = (const float*)d_in[10];
    float*       out  = (float*)d_out;

    cudaFuncSetAttribute(k_gemm<SEL_X,  SEL_H1>, cudaFuncAttributeMaxDynamicSharedMemorySize, SMEM_DYN);
    cudaFuncSetAttribute(k_gemm<SEL_H1, SEL_H2>, cudaFuncAttributeMaxDynamicSharedMemorySize, SMEM_DYN);
    cudaFuncSetAttribute(k_gemm<SEL_H2, SEL_X >, cudaFuncAttributeMaxDynamicSharedMemorySize, SMEM_DYN);

    const int TB = 256;
    k_prep <<<NB_X2H + NB_INIT + NB_TR, TB>>>(x, W1_0, W1_1, W2_0, W2_1, W3_0, W3_1);
    k_deg  <<<(NEDGES + TB - 1) / TB, TB>>>(ei);
    k_scan1<<<SCAN_BLOCKS, 1024>>>();
    k_fill <<<(NEDGES + TB - 1) / TB, TB>>>(ei);

    dim3 ggrid(MP / BM, NOUT / BN);   // 391 x 2
    const int spmmGrid = (NNODES + SPMM_RPB - 1) / SPMM_RPB;   // 1563

    // layer 1 (K = 128): W8=16 -> 8 slices need 128 threads
    k_spmm<128, SEL_X><<<spmmGrid, 128>>>(0);
    k_gemm<SEL_X, SEL_H1><<<ggrid, 256, SMEM_DYN>>>(WT_OFF_10, WT_OFF_11, b1, nullptr, 128, 1);

    // layer 2 (K = 256): W8=32 -> 8 slices need 256 threads
    k_spmm<256, SEL_H1><<<spmmGrid, 256>>>(0);
    k_gemm<SEL_H1, SEL_H2><<<ggrid, 256, SMEM_DYN>>>(WT_OFF_20, WT_OFF_21, b2, nullptr, 256, 1);

    // layer 3 (K = 256), no relu, fp32 store into d_out
    k_spmm<256, SEL_H2><<<spmmGrid, 256>>>(0);
    k_gemm<SEL_H2, SEL_X><<<ggrid, 256, SMEM_DYN>>>(WT_OFF_30, WT_OFF_31, b3, out, 256, 0);
}

// round 17
// speedup vs baseline: 1.0104x; 1.0104x over previous
#include <cuda_runtime.h>
#include <cuda_fp16.h>
#include <cstdint>

#define NNODES 50000
#define NEDGES 400000
#define MP     50048
#define NOUT   256
#define SCAN_BLOCKS 49    // 49*1024 >= NNODES+1

// ---------------- static device scratch (no allocations allowed) ----------------
__device__ int    g_deg[NNODES];
__device__ int    g_cnt[NNODES];
__device__ int    g_fill[NNODES];
__device__ float  g_dinv[NNODES];
__device__ int    g_rowptr[NNODES + 1];   // block-LOCAL exclusive scan
__device__ int    g_bsum[SCAN_BLOCKS];
__device__ int    g_boff[SCAN_BLOCKS];    // global offset of each scan block
__device__ int    g_done;                 // scan1 completion counter
__device__ int    g_col[NEDGES];
__device__ float  g_wval[NEDGES];
// fp16 activation / weight storage
__device__ __half g_xh  [(size_t)MP * 128];
__device__ __half g_h1h [(size_t)MP * 256];
__device__ __half g_h2h [(size_t)MP * 256];
__device__ __half g_aggh[(size_t)MP * 256];
__device__ __half g_wth [256 * 128 * 2 + 256 * 256 * 4];   // Wt[n][k] fp16

#define WT_OFF_10 0
#define WT_OFF_11 (256 * 128)
#define WT_OFF_20 (256 * 128 * 2)
#define WT_OFF_21 (WT_OFF_20 + 256 * 256)
#define WT_OFF_30 (WT_OFF_21 + 256 * 256)
#define WT_OFF_31 (WT_OFF_30 + 256 * 256)

#define SEL_X   0
#define SEL_H1  1
#define SEL_H2  2

__device__ __forceinline__ const __half* sel_ch(int SEL) {
    switch (SEL) {
        case SEL_H1: return g_h1h;
        case SEL_H2: return g_h2h;
        default:     return g_xh;
    }
}

// ---------------- mma / ldmatrix / cp.async helpers ----------------
__device__ __forceinline__ void mma_f16(float* c, const uint32_t* a, const uint32_t* b) {
    asm volatile(
        "mma.sync.aligned.m16n8k16.row.col.f32.f16.f16.f32 "
        "{%0,%1,%2,%3}, {%4,%5,%6,%7}, {%8,%9}, {%0,%1,%2,%3};"
        : "+f"(c[0]), "+f"(c[1]), "+f"(c[2]), "+f"(c[3])
        : "r"(a[0]), "r"(a[1]), "r"(a[2]), "r"(a[3]), "r"(b[0]), "r"(b[1]));
}
__device__ __forceinline__ void ldsm_x4(uint32_t& r0, uint32_t& r1, uint32_t& r2,
                                        uint32_t& r3, uint32_t addr) {
    asm volatile("ldmatrix.sync.aligned.m8n8.x4.shared.b16 {%0,%1,%2,%3}, [%4];"
                 : "=r"(r0), "=r"(r1), "=r"(r2), "=r"(r3) : "r"(addr));
}
__device__ __forceinline__ uint32_t smem_u32(const void* p) {
    uint32_t a;
    asm("{ .reg .u64 t; cvta.to.shared.u64 t, %1; cvt.u32.u64 %0, t; }" : "=r"(a) : "l"(p));
    return a;
}
__device__ __forceinline__ void cp_async16(uint32_t dst, const void* src, bool valid) {
    int sz = valid ? 16 : 0;   // src-size 0 -> zero-fill
    asm volatile("cp.async.cg.shared.global [%0], [%1], 16, %2;"
                 :: "r"(dst), "l"(src), "r"(sz) : "memory");
}
#define CP_COMMIT()  asm volatile("cp.async.commit_group;" ::: "memory")
#define CP_WAIT2()   asm volatile("cp.async.wait_group 2;" ::: "memory")
#define CP_WAIT1()   asm volatile("cp.async.wait_group 1;" ::: "memory")
#define CP_WAIT0()   asm volatile("cp.async.wait_group 0;" ::: "memory")

// ---------------- fused prep: init counters + x->fp16 + weight transpose ---------
#define NB_X2H 12512                      // MP*64 half2 / 256
#define NB_INIT 196                       // ceil(NNODES/256)
#define NB_TR   384                       // 6 matrices * 8 kb * 8 nb
__global__ void k_prep(const float* __restrict__ x,
                       const float* __restrict__ w10, const float* __restrict__ w11,
                       const float* __restrict__ w20, const float* __restrict__ w21,
                       const float* __restrict__ w30, const float* __restrict__ w31)
{
    const int b = blockIdx.x;
    if (b < NB_X2H) {
        // x -> fp16 with zero padding
        const size_t i = (size_t)b * 256 + threadIdx.x;   // half2 index
        int row = (int)(i >> 6);
        __half2 v = __float2half2_rn(0.f);
        if (row < NNODES) {
            float2 f = reinterpret_cast<const float2*>(x)[i];
            v = __floats2half2_rn(f.x, f.y);
        }
        reinterpret_cast<__half2*>(g_xh)[i] = v;
    } else if (b < NB_X2H + NB_INIT) {
        const int i = (b - NB_X2H) * 256 + threadIdx.x;
        if (i < NNODES) { g_deg[i] = 0; g_cnt[i] = 0; g_fill[i] = 0; }
        if (i == 0) g_done = 0;
    } else {
        // weight transpose + fp16: g_wth[n][k] = W[k][n]
        __shared__ float sh[32][33];
        const int idx = b - (NB_X2H + NB_INIT);
        const int m   = idx / 64;
        const int rem = idx % 64;
        const int kb  = (rem / 8) * 32;
        const int nb  = (rem % 8) * 32;
        const float* W; int K, off;
        switch (m) {
            case 0: W = w10; K = 128; off = WT_OFF_10; break;
            case 1: W = w11; K = 128; off = WT_OFF_11; break;
            case 2: W = w20; K = 256; off = WT_OFF_20; break;
            case 3: W = w21; K = 256; off = WT_OFF_21; break;
            case 4: W = w30; K = 256; off = WT_OFF_30; break;
            default: W = w31; K = 256; off = WT_OFF_31; break;
        }
        if (kb >= K) return;
        const int tx = threadIdx.x & 31, ty0 = threadIdx.x >> 5;   // 32 x 8
        for (int ty = ty0; ty < 32; ty += 8)
            sh[ty][tx] = W[(size_t)(kb + ty) * NOUT + nb + tx];
        __syncthreads();
        for (int ty = ty0; ty < 32; ty += 8)
            g_wth[(size_t)off + (size_t)(nb + ty) * K + kb + tx] = __float2half(sh[tx][ty]);
    }
}

// edge_index is int32 (JAX default config disables x64)
__global__ void k_deg(const int* __restrict__ ei) {
    int e = blockIdx.x * blockDim.x + threadIdx.x;
    if (e < NEDGES) {
        int s = ei[e];
        int d = ei[NEDGES + e];
        if (s != d && (unsigned)s < NNODES && (unsigned)d < NNODES) {
            atomicAdd(&g_deg[s], 1);
            atomicAdd(&g_cnt[d], 1);
        }
    }
}

// scan phase 1: block-local exclusive scan via warp shuffles; dinv; and the
// LAST block to finish also scans the 49 block sums into g_boff (no extra launch).
__global__ void k_scan1() {
    __shared__ int wsum[32];
    __shared__ int lastFlag;
    const int t    = threadIdx.x;
    const int lane = t & 31;
    const int wid  = t >> 5;
    const int i    = blockIdx.x * 1024 + t;

    if (i < NNODES) {
        int dg = g_deg[i];
        g_dinv[i] = (dg > 0) ? rsqrtf((float)dg) : 0.0f;
    }

    int v = (i < NNODES) ? g_cnt[i] : 0;
    // inclusive warp scan
    int x = v;
#pragma unroll
    for (int off = 1; off < 32; off <<= 1) {
        int y = __shfl_up_sync(0xFFFFFFFFu, x, off);
        if (lane >= off) x += y;
    }
    if (lane == 31) wsum[wid] = x;
    __syncthreads();
    if (wid == 0) {
        int s = wsum[lane];
#pragma unroll
        for (int off = 1; off < 32; off <<= 1) {
            int y = __shfl_up_sync(0xFFFFFFFFu, s, off);
            if (lane >= off) s += y;
        }
        wsum[lane] = s;   // inclusive over warp sums
    }
    __syncthreads();
    int prefix = ((wid > 0) ? wsum[wid - 1] : 0) + (x - v);   // block-local exclusive
    if (i <= NNODES) g_rowptr[i] = prefix;
    if (t == 1023) g_bsum[blockIdx.x] = wsum[31];

    // last-block-done: scan the block sums into g_boff
    __syncthreads();   // ensure g_bsum store by t=1023 is ordered below
    if (t == 0) {
        __threadfence();
        int prev = atomicAdd(&g_done, 1);
        lastFlag = (prev == SCAN_BLOCKS - 1) ? 1 : 0;
    }
    __syncthreads();
    if (lastFlag && t == 0) {
        int s = 0;
        for (int b = 0; b < SCAN_BLOCKS; ++b) { g_boff[b] = s; s += g_bsum[b]; }
        __threadfence();
    }
}

__global__ void k_fill(const int* __restrict__ ei) {
    int e = blockIdx.x * blockDim.x + threadIdx.x;
    if (e < NEDGES) {
        int s = ei[e];
        int d = ei[NEDGES + e];
        if (s != d && (unsigned)s < NNODES && (unsigned)d < NNODES) {
            int pos = atomicAdd(&g_fill[d], 1);
            int idx = g_rowptr[d] + g_boff[d >> 10] + pos;
            g_col[idx]  = s;
            g_wval[idx] = -g_dinv[s] * g_dinv[d];
        }
    }
}

// ---------------- SpMM (fp16 in/out, fp32 accum) ----------------
// 8 rows per block; each row handled by W8 = F/8 lanes (one uint4 per lane).
// Edge loop unrolled x4 for MLP.  (R15 configuration — proven fastest.)
#define SPMM_ROWS 8
template <int F, int SEL_IN>
__global__ void k_spmm(int dummy) {
    const uint4* __restrict__ in = reinterpret_cast<const uint4*>(sel_ch(SEL_IN));
    const int W8  = F / 8;
    const int row = blockIdx.x * SPMM_ROWS + threadIdx.x / W8;
    const int t   = threadIdx.x % W8;
    if (row >= NNODES) return;
    const int beg = g_rowptr[row]     + g_boff[row >> 10];
    const int end = g_rowptr[row + 1] + g_boff[(row + 1) >> 10];

    float ac[8];
#pragma unroll
    for (int q = 0; q < 8; ++q) ac[q] = 0.f;

    int j = beg;
    for (; j + 3 < end; j += 4) {
        float w0 = g_wval[j];     int c0 = g_col[j];
        float w1 = g_wval[j + 1]; int c1 = g_col[j + 1];
        float w2 = g_wval[j + 2]; int c2 = g_col[j + 2];
        float w3 = g_wval[j + 3]; int c3 = g_col[j + 3];
        uint4 v0 = __ldg(&in[(size_t)c0 * W8 + t]);
        uint4 v1 = __ldg(&in[(size_t)c1 * W8 + t]);
        uint4 v2 = __ldg(&in[(size_t)c2 * W8 + t]);
        uint4 v3 = __ldg(&in[(size_t)c3 * W8 + t]);
        const __half2* h0 = reinterpret_cast<const __half2*>(&v0);
        const __half2* h1 = reinterpret_cast<const __half2*>(&v1);
        const __half2* h2 = reinterpret_cast<const __half2*>(&v2);
        const __half2* h3 = reinterpret_cast<const __half2*>(&v3);
#pragma unroll
        for (int q = 0; q < 4; ++q) {
            float2 f0 = __half22float2(h0[q]);
            float2 f1 = __half22float2(h1[q]);
            float2 f2 = __half22float2(h2[q]);
            float2 f3 = __half22float2(h3[q]);
            ac[2*q]   += (w0 * f0.x + w1 * f1.x) + (w2 * f2.x + w3 * f3.x);
            ac[2*q+1] += (w0 * f0.y + w1 * f1.y) + (w2 * f2.y + w3 * f3.y);
        }
    }
    for (; j < end; ++j) {
        float w = g_wval[j]; int c = g_col[j];
        uint4 v = __ldg(&in[(size_t)c * W8 + t]);
        const __half2* h = reinterpret_cast<const __half2*>(&v);
#pragma unroll
        for (int q = 0; q < 4; ++q) {
            float2 f = __half22float2(h[q]);
            ac[2*q]   += w * f.x;
            ac[2*q+1] += w * f.y;
        }
    }

    uint4 o;
    __half2* oh = reinterpret_cast<__half2*>(&o);
#pragma unroll
    for (int q = 0; q < 4; ++q) oh[q] = __floats2half2_rn(ac[2*q], ac[2*q+1]);
    reinterpret_cast<uint4*>(g_aggh)[(size_t)row * W8 + t] = o;
}

// ---------------- fp16 HMMA fused dual-GEMM: cp.async 4-stage, swizzled ----------
#define BM 128
#define BN 128
#define BK 32
#define STG_WORDS (128 * 16)        // words per stage per operand
#define STG_BYTES (STG_WORDS * 4)   // 8192
#define NSTG 4
#define SMEM_DYN (NSTG * 2 * STG_BYTES)   // 65536

template <int SEL_A0, int SEL_C>
__global__ void __launch_bounds__(256, 2) k_gemm(
    int wtOff0, int wtOff1,
    const float* __restrict__ bias, float* __restrict__ C_ext,
    int K, int do_relu)
{
    extern __shared__ uint32_t smem_dyn[];
    const __half* __restrict__ A0 = sel_ch(SEL_A0);
    const __half* __restrict__ A1 = g_aggh;
    const __half* __restrict__ W0 = g_wth + wtOff0;
    const __half* __restrict__ W1 = g_wth + wtOff1;

    const int tid  = threadIdx.x;        // 0..255
    const int warp = tid >> 5;           // 0..7
    const int lane = tid & 31;
    const int gid  = lane >> 2;          // 0..7
    const int tig  = lane & 3;           // 0..3
    const int wm   = (warp & 3)  * 32;   // warp row offset (4 m-warps)
    const int wn   = (warp >> 2) * 64;   // warp col offset (2 n-warps)

    const int rowBase = blockIdx.x * BM;
    const int colBase = blockIdx.y * BN;

    // stager: row = tid>>1 (0..127); groups (tid&1)*2 + {0,1} (each 8 halves = 16B)
    const int sRow = tid >> 1;
    const int g0   = (tid & 1) * 2;
    const int swz  = (sRow >> 1) & 3;
    const bool aValid = (rowBase + sRow < NNODES);
    const __half* __restrict__ Arow0 = A0 + (size_t)(rowBase + sRow) * K;
    const __half* __restrict__ Arow1 = A1 + (size_t)(rowBase + sRow) * K;
    const __half* __restrict__ Brow0 = W0 + (size_t)(colBase + sRow) * K;
    const __half* __restrict__ Brow1 = W1 + (size_t)(colBase + sRow) * K;

    // ldmatrix lane addressing
    const int aLRow = wm + (lane & 7) + ((lane >> 3) & 1) * 8;   // + mt*16
    const int aG    = lane >> 4;                                  // k-group within k16
    const int bLRow = wn + (lane & 7) + (lane >> 4) * 8;          // + ntp*16
    const int bG    = (lane >> 3) & 1;

    const uint32_t asBase = smem_u32(&smem_dyn[0]);
    const uint32_t bsBase = asBase + NSTG * STG_BYTES;

    const int Kt = K / BK;     // tiles per pass
    const int T  = 2 * Kt;     // A0 pass then agg pass (T = 8 or 16)

    float acc[2][8][4];
#pragma unroll
    for (int mt = 0; mt < 2; ++mt)
#pragma unroll
        for (int nt = 0; nt < 8; ++nt)
#pragma unroll
            for (int q = 0; q < 4; ++q) acc[mt][nt][q] = 0.0f;

    // issue stage tn into ring buffer `buf`
    auto issue = [&](int tn, int buf) {
        const bool p2 = (tn >= Kt);
        const __half* __restrict__ Ar = p2 ? Arow1 : Arow0;
        const __half* __restrict__ Br = p2 ? Brow1 : Brow0;
        const int k0 = (tn - (p2 ? Kt : 0)) * BK;
        const uint32_t aB = asBase + (uint32_t)buf * STG_BYTES;
        const uint32_t bB = bsBase + (uint32_t)buf * STG_BYTES;
#pragma unroll
        for (int q = 0; q < 2; ++q) {
            const int g  = g0 + q;
            const int gp = g ^ swz;
            const uint32_t dOff = (uint32_t)((sRow * 16 + gp * 4) * 4);
            cp_async16(aB + dOff, Ar + k0 + g * 8, aValid);
            cp_async16(bB + dOff, Br + k0 + g * 8, true);
        }
        CP_COMMIT();
    };

    issue(0, 0);
    if (T > 1) issue(1, 1);
    if (T > 2) issue(2, 2);

#pragma unroll 1
    for (int t = 0; t < T; ++t) {
        if (t + 3 <= T - 1)      { CP_WAIT2(); }
        else if (t + 2 <= T - 1) { CP_WAIT1(); }
        else                     { CP_WAIT0(); }
        __syncthreads();
        // top barrier also seals all reads of buffer (t-1)%4 (done in iter t-1),
        // so the issue below may overwrite it; no bottom barrier needed.

        if (t + 3 < T) issue(t + 3, (t + 3) & (NSTG - 1));

        const uint32_t asC = asBase + (uint32_t)(t & (NSTG - 1)) * STG_BYTES;
        const uint32_t bsC = bsBase + (uint32_t)(t & (NSTG - 1)) * STG_BYTES;

#pragma unroll
        for (int kh = 0; kh < 2; ++kh) {
            uint32_t a[2][4], b[8][2];
#pragma unroll
            for (int mt = 0; mt < 2; ++mt) {
                const int row = aLRow + mt * 16;
                const int gp  = (kh * 2 + aG) ^ ((row >> 1) & 3);
                ldsm_x4(a[mt][0], a[mt][1], a[mt][2], a[mt][3],
                        asC + (uint32_t)((row * 16 + gp * 4) * 4));
            }
#pragma unroll
            for (int ntp = 0; ntp < 4; ++ntp) {
                const int row = bLRow + ntp * 16;
                const int gp  = (kh * 2 + bG) ^ ((row >> 1) & 3);
                ldsm_x4(b[2*ntp][0], b[2*ntp][1], b[2*ntp+1][0], b[2*ntp+1][1],
                        bsC + (uint32_t)((row * 16 + gp * 4) * 4));
            }
#pragma unroll
            for (int mt = 0; mt < 2; ++mt)
#pragma unroll
                for (int nt = 0; nt < 8; ++nt)
                    mma_f16(acc[mt][nt], a[mt], b[nt]);
        }
    }

    // ---- epilogue: bias + optional relu ----
    float2 bb[8];
#pragma unroll
    for (int nt = 0; nt < 8; ++nt)
        bb[nt] = *reinterpret_cast<const float2*>(&bias[colBase + wn + nt * 8 + 2 * tig]);

    if (SEL_C == SEL_X) {
        float* __restrict__ C = C_ext;
#pragma unroll
        for (int mt = 0; mt < 2; ++mt) {
            const int r0 = rowBase + wm + mt * 16 + gid;
            const int r1 = r0 + 8;
#pragma unroll
            for (int nt = 0; nt < 8; ++nt) {
                const int c = colBase + wn + nt * 8 + 2 * tig;
                float v0 = acc[mt][nt][0] + bb[nt].x;
                float v1 = acc[mt][nt][1] + bb[nt].y;
                float v2 = acc[mt][nt][2] + bb[nt].x;
                float v3 = acc[mt][nt][3] + bb[nt].y;
                if (do_relu) {
                    v0 = fmaxf(v0, 0.f); v1 = fmaxf(v1, 0.f);
                    v2 = fmaxf(v2, 0.f); v3 = fmaxf(v3, 0.f);
                }
                if (r0 < NNODES)
                    *reinterpret_cast<float2*>(&C[(size_t)r0 * NOUT + c]) = make_float2(v0, v1);
                if (r1 < NNODES)
                    *reinterpret_cast<float2*>(&C[(size_t)r1 * NOUT + c]) = make_float2(v2, v3);
            }
        }
    } else {
        __half* __restrict__ Ch = (SEL_C == SEL_H1) ? g_h1h : g_h2h;
#pragma unroll
        for (int mt = 0; mt < 2; ++mt) {
            const int r0 = rowBase + wm + mt * 16 + gid;
            const int r1 = r0 + 8;
#pragma unroll
            for (int nt = 0; nt < 8; ++nt) {
                const int c = colBase + wn + nt * 8 + 2 * tig;
                float v0 = acc[mt][nt][0] + bb[nt].x;
                float v1 = acc[mt][nt][1] + bb[nt].y;
                float v2 = acc[mt][nt][2] + bb[nt].x;
                float v3 = acc[mt][nt][3] + bb[nt].y;
                if (do_relu) {
                    v0 = fmaxf(v0, 0.f); v1 = fmaxf(v1, 0.f);
                    v2 = fmaxf(v2, 0.f); v3 = fmaxf(v3, 0.f);
                }
                *reinterpret_cast<__half2*>(&Ch[(size_t)r0 * NOUT + c]) = __floats2half2_rn(v0, v1);
                *reinterpret_cast<__half2*>(&Ch[(size_t)r1 * NOUT + c]) = __floats2half2_rn(v2, v3);
            }
        }
    }
}

// ---------------- launcher ----------------
extern "C" void kernel_launch(void* const* d_in, const int* in_sizes, int n_in,
                              void* d_out, int out_size)
{
    const float* x    = (const float*)d_in[0];
    const int*   ei   = (const int*)d_in[1];     // int32 (JAX x64 disabled)
    const float* W1_0 = (const float*)d_in[2];
    const float* W1_1 = (const float*)d_in[3];
    const float* b1   = (const float*)d_in[4];
    const float* W2_0 = (const float*)d_in[5];
    const float* W2_1 = (const float*)d_in[6];
    const float* b2   = (const float*)d_in[7];
    const float* W3_0 = (const float*)d_in[8];
    const float* W3_1 = (const float*)d_in[9];
    const float* b3   = (const float*)d_in[10];
    float*       out  = (float*)d_out;

    cudaFuncSetAttribute(k_gemm<SEL_X,  SEL_H1>, cudaFuncAttributeMaxDynamicSharedMemorySize, SMEM_DYN);
    cudaFuncSetAttribute(k_gemm<SEL_H1, SEL_H2>, cudaFuncAttributeMaxDynamicSharedMemorySize, SMEM_DYN);
    cudaFuncSetAttribute(k_gemm<SEL_H2, SEL_X >, cudaFuncAttributeMaxDynamicSharedMemorySize, SMEM_DYN);

    const int TB = 256;
    k_prep <<<NB_X2H + NB_INIT + NB_TR, TB>>>(x, W1_0, W1_1, W2_0, W2_1, W3_0, W3_1);
    k_deg  <<<(NEDGES + TB - 1) / TB, TB>>>(ei);
    k_scan1<<<SCAN_BLOCKS, 1024>>>();
    k_fill <<<(NEDGES + TB - 1) / TB, TB>>>(ei);

    dim3 ggrid(MP / BM, NOUT / BN);   // 391 x 2
    const int spmmGrid = (NNODES + SPMM_ROWS - 1) / SPMM_ROWS;   // 6250

    // layer 1 (K = 128): W8=16 lanes/row, 8 rows -> 128 threads
    k_spmm<128, SEL_X><<<spmmGrid, 128>>>(0);
    k_gemm<SEL_X, SEL_H1><<<ggrid, 256, SMEM_DYN>>>(WT_OFF_10, WT_OFF_11, b1, nullptr, 128, 1);

    // layer 2 (K = 256): W8=32 lanes/row, 8 rows -> 256 threads
    k_spmm<256, SEL_H1><<<spmmGrid, 256>>>(0);
    k_gemm<SEL_H1, SEL_H2><<<ggrid, 256, SMEM_DYN>>>(WT_OFF_20, WT_OFF_21, b2, nullptr, 256, 1);

    // layer 3 (K = 256), no relu, fp32 store into d_out
    k_spmm<256, SEL_H2><<<spmmGrid, 256>>>(0);
    k_gemm<SEL_H2, SEL_X><<<ggrid, 256, SMEM_DYN>>>(WT_OFF_30, WT_OFF_31, b3, out, 256, 0);
}